// round 8
// baseline (speedup 1.0000x reference)
#include <cuda_runtime.h>
#include <cuda_bf16.h>
#include <cstdint>

// Closed-form per-(batch,class) reduction of the symmetric-pair loss.
// For a group of n points of one symmetric class (c in {0,1,2}), with
// u_i = x_i - CENTER_X:
//   sum_{i<j} (u_i+u_j)^2 = (n-2)*Sum(u^2) + (Sum u)^2
//   sum_{i<j} (y_i-y_j)^2 =  n   *Sum(y^2) - (Sum y)^2
//   #pairs                =  n(n-1)/2
// Both identities are exactly 0 for n in {0,1}.
//
// kernel1: 256 CTAs x 256 threads (R5-proven shape: 2 points/thread,
//          float4+int2 loads), 12 float accumulators via shuffle +
//          3 int counts via REDUX, warp-parallel cross-warp combine,
//          all-float closed form.
// finalize: PDL-overlapped single warp; double only for the final
//          256-element accumulation.

#define CENTER_X 0.5f
#define BATCH 256
#define NPTS  512

__device__ float2 g_partial[BATCH];  // (loss, count) per batch

__global__ void __launch_bounds__(256) sym_per_batch(const float* __restrict__ kp,
                                                     const int* __restrict__ cls) {
    const int b = blockIdx.x;
    const int t = threadIdx.x;

    // Each thread handles 2 consecutive points: 1x float4 + 1x int2.
    const float4 p = reinterpret_cast<const float4*>(kp)[(size_t)b * 256 + t];
    const int2   c = reinterpret_cast<const int2*>(cls)[(size_t)b * 256 + t];

    float su[3], su2[3], sy[3], sy2[3];
    int   cn[3];
#pragma unroll
    for (int k = 0; k < 3; k++) { su[k] = su2[k] = sy[k] = sy2[k] = 0.0f; cn[k] = 0; }

    const float ux[2] = {p.x - CENTER_X, p.z - CENTER_X};
    const float yy[2] = {p.y, p.w};
    const int   cc[2] = {c.x, c.y};
#pragma unroll
    for (int j = 0; j < 2; j++) {
#pragma unroll
        for (int k = 0; k < 3; k++) {
            if (cc[j] == k) {
                su[k]  += ux[j];
                su2[k]  = fmaf(ux[j], ux[j], su2[k]);
                sy[k]  += yy[j];
                sy2[k]  = fmaf(yy[j], yy[j], sy2[k]);
                cn[k]  += 1;
            }
        }
    }

    // Intra-warp reduction: 12 float accumulators via shuffles,
    // 3 int counts via single-instruction REDUX.
#pragma unroll
    for (int off = 16; off > 0; off >>= 1) {
#pragma unroll
        for (int k = 0; k < 3; k++) {
            su[k]  += __shfl_down_sync(0xffffffffu, su[k],  off);
            su2[k] += __shfl_down_sync(0xffffffffu, su2[k], off);
            sy[k]  += __shfl_down_sync(0xffffffffu, sy[k],  off);
            sy2[k] += __shfl_down_sync(0xffffffffu, sy2[k], off);
        }
    }
    int cnt[3];
#pragma unroll
    for (int k = 0; k < 3; k++)
        cnt[k] = __reduce_add_sync(0xffffffffu, cn[k]);

    // Cross-warp: 8 warps publish 15 values each.
    __shared__ float sf[8][16];  // padded row
    __shared__ float stot[16];
    const int wid = t >> 5, lid = t & 31;
    if (lid == 0) {
#pragma unroll
        for (int k = 0; k < 3; k++) {
            sf[wid][k * 4 + 0] = su[k];
            sf[wid][k * 4 + 1] = su2[k];
            sf[wid][k * 4 + 2] = sy[k];
            sf[wid][k * 4 + 3] = sy2[k];
            sf[wid][12 + k]    = (float)cnt[k];
        }
    }
    __syncthreads();

    // Warp 0, lanes 0..14: each lane sums one accumulator type across 8 warps.
    if (wid == 0) {
        if (lid < 15) {
            float s = 0.0f;
#pragma unroll
            for (int w = 0; w < 8; w++) s += sf[w][lid];
            stot[lid] = s;
        }
        __syncwarp();
        if (lid == 0) {
            float loss = 0.0f, count = 0.0f;
#pragma unroll
            for (int k = 0; k < 3; k++) {
                const float SU  = stot[k * 4 + 0];
                const float SU2 = stot[k * 4 + 1];
                const float SY  = stot[k * 4 + 2];
                const float SY2 = stot[k * 4 + 3];
                const float n   = stot[12 + k];
                loss  += (n - 2.0f) * SU2 + SU * SU + n * SY2 - SY * SY;
                count += n * (n - 1.0f) * 0.5f;
            }
            g_partial[b] = make_float2(loss, count);
        }
    }

#if __CUDA_ARCH__ >= 900
    cudaTriggerProgrammaticLaunchCompletion();
#endif
}

__global__ void __launch_bounds__(32) sym_finalize(float* __restrict__ out) {
#if __CUDA_ARCH__ >= 900
    cudaGridDependencySynchronize();  // full visibility of g_partial
#endif
    const int l = threadIdx.x;
    // 256 float2 partials = 128 float4; each lane reads 4 coalesced float4.
    const float4* p4 = reinterpret_cast<const float4*>(g_partial);
    double L = 0.0, C = 0.0;
#pragma unroll
    for (int i = 0; i < 4; i++) {
        const float4 v = p4[l + 32 * i];
        L += (double)v.x + (double)v.z;
        C += (double)v.y + (double)v.w;
    }
#pragma unroll
    for (int off = 16; off > 0; off >>= 1) {
        L += __shfl_down_sync(0xffffffffu, L, off);
        C += __shfl_down_sync(0xffffffffu, C, off);
    }
    if (l == 0) {
        const double c = C < 1.0 ? 1.0 : C;
        out[0] = (float)(L / c);
    }
}

extern "C" void kernel_launch(void* const* d_in, const int* in_sizes, int n_in,
                              void* d_out, int out_size) {
    const float* kp  = (const float*)d_in[0];  // [256, 512, 2] f32
    const int*   cls = (const int*)d_in[1];    // [256, 512] i32
    float* out = (float*)d_out;

    sym_per_batch<<<BATCH, 256>>>(kp, cls);

    // Finalize with Programmatic Dependent Launch to overlap launch latency.
    cudaLaunchConfig_t cfg = {};
    cfg.gridDim  = dim3(1, 1, 1);
    cfg.blockDim = dim3(32, 1, 1);
    cfg.dynamicSmemBytes = 0;
    cfg.stream = 0;
    cudaLaunchAttribute attr[1];
    attr[0].id = cudaLaunchAttributeProgrammaticStreamSerialization;
    attr[0].val.programmaticStreamSerializationAllowed = 1;
    cfg.attrs = attr;
    cfg.numAttrs = 1;

    cudaError_t e = cudaLaunchKernelEx(&cfg, sym_finalize, out);
    if (e != cudaSuccess) {
        sym_finalize<<<1, 32>>>(out);
    }
}